// round 11
// baseline (speedup 1.0000x reference)
#include <cuda_runtime.h>

#define NN 100000
#define NE 1600000
#define NB 98   // ceil(NN/1024)

// -------- static scratch (no allocations) --------
__device__ float4 d_xs4[NN * 16];   // staged x (DIAGNOSTIC: written, never read)
__device__ int    d_deg[NN];        // invariant: zero at entry (re-zeroed by scanC)
__device__ int    d_off[NN + 1];
__device__ int    d_cur[NN];
__device__ float  d_dinv[NN];
__device__ int    d_csr[NE];
__device__ float  d_csrw[NE];       // dinv[src] per CSR slot
__device__ float4 d_bufA[NN * 16];
__device__ float4 d_bufB[NN * 16];
__device__ float2 d_g[NN];
__device__ float  d_C[96];
__device__ int    d_part[NB];
__device__ int    d_poff[NB];

// -------- 0: stage x into HBM (diagnostic this round; output unused) --------
__global__ void k_stageX(const float4* __restrict__ x)
{
    int i = blockIdx.x * 256 + threadIdx.x;
    if (i < NN * 16) d_xs4[i] = x[i];
}

// -------- 1: degree count, 4 edges/thread --------
__global__ void k_count(const int* __restrict__ dst)
{
    int base = (blockIdx.x * 256 + threadIdx.x) * 4;
    if (base < NE) {
        int4 d4 = *(const int4*)(dst + base);
        atomicAdd(&d_deg[d4.x], 1);
        atomicAdd(&d_deg[d4.y], 1);
        atomicAdd(&d_deg[d4.z], 1);
        atomicAdd(&d_deg[d4.w], 1);
    }
}

// -------- 2: per-1024-chunk partial sums --------
__global__ void k_scanA()
{
    __shared__ int sred[1024];
    int t = threadIdx.x;
    int i = blockIdx.x * 1024 + t;
    sred[t] = (i < NN) ? d_deg[i] : 0;
    __syncthreads();
#pragma unroll
    for (int o = 512; o > 0; o >>= 1) {
        if (t < o) sred[t] += sred[t + o];
        __syncthreads();
    }
    if (t == 0) d_part[blockIdx.x] = sred[0];
}

// -------- 3: scan the 98 partials + constant-table prep --------
__global__ void k_scanB(const float* __restrict__ emb0, const float* __restrict__ emb1,
                        const float* __restrict__ fcW1, const float* __restrict__ fcb1,
                        const float* __restrict__ fcW2, const float* __restrict__ fcb2)
{
    int t = threadIdx.x;
    if (t < 40) {
        int i = t >> 1, j = t & 1;
        float s = 0.f;
#pragma unroll
        for (int k = 0; k < 32; k++) s = fmaf(emb0[i * 32 + k], fcW1[(66 + k) * 2 + j], s);
        d_C[t] = s;
    } else if (t < 80) {
        int u = t - 40;
        int i = u >> 1, j = u & 1;
        float s = 0.f;
#pragma unroll
        for (int k = 0; k < 32; k++) s = fmaf(emb1[i * 32 + k], fcW1[(98 + k) * 2 + j], s);
        d_C[t] = s;
    } else if (t < 92) {
        int u = t - 80;
        float v;
        if (u < 4)       v = fcW1[128 + u];
        else if (u < 6)  v = fcb1[u - 4];
        else if (u < 10) v = fcW2[u - 6];
        else             v = fcb2[u - 10];
        d_C[t] = v;
    }
    if (t == 127) {
        int run = 0;
#pragma unroll 7
        for (int i = 0; i < NB; i++) { int v = d_part[i]; d_poff[i] = run; run += v; }
        d_off[NN] = run;
    }
}

// -------- GEMM (round-4 verbatim): Z = X @ W. 2 threads/node, prefetch 8 float4 --------
__global__ void __launch_bounds__(256) k_gemm(const float* __restrict__ X,
                                              const float* __restrict__ W,
                                              float* __restrict__ Z)
{
    __shared__ float Ws[4096];
    {
        const float4* W4 = (const float4*)W;
        float4* Ws4 = (float4*)Ws;
        for (int i = threadIdx.x; i < 1024; i += 256) Ws4[i] = W4[i];
    }
    __syncthreads();

    int idx = blockIdx.x * 256 + threadIdx.x;
    int n = idx >> 1, half = idx & 1;
    if (n >= NN) return;

    const float4* xr = (const float4*)(X + (size_t)n * 64);
    float acc[32];
#pragma unroll
    for (int j = 0; j < 32; j++) acc[j] = 0.f;

#pragma unroll
    for (int hblk = 0; hblk < 2; hblk++) {
        float4 xv[8];
#pragma unroll
        for (int i = 0; i < 8; i++) xv[i] = xr[hblk * 8 + i];
#pragma unroll
        for (int i = 0; i < 8; i++) {
            int k4 = hblk * 8 + i;
#pragma unroll
            for (int kk = 0; kk < 4; kk++) {
                float xs = (kk == 0) ? xv[i].x : (kk == 1) ? xv[i].y : (kk == 2) ? xv[i].z : xv[i].w;
                const float4* wr = (const float4*)(Ws + (k4 * 4 + kk) * 64 + half * 32);
#pragma unroll
                for (int j4 = 0; j4 < 8; j4++) {
                    float4 w = wr[j4];
                    acc[j4 * 4 + 0] = fmaf(xs, w.x, acc[j4 * 4 + 0]);
                    acc[j4 * 4 + 1] = fmaf(xs, w.y, acc[j4 * 4 + 1]);
                    acc[j4 * 4 + 2] = fmaf(xs, w.z, acc[j4 * 4 + 2]);
                    acc[j4 * 4 + 3] = fmaf(xs, w.w, acc[j4 * 4 + 3]);
                }
            }
        }
    }

    float4* zr = (float4*)(Z + (size_t)n * 64 + half * 32);
#pragma unroll
    for (int j4 = 0; j4 < 8; j4++)
        zr[j4] = make_float4(acc[j4 * 4], acc[j4 * 4 + 1], acc[j4 * 4 + 2], acc[j4 * 4 + 3]);
}

// -------- 5: offsets/cursor/dinv via block scan + re-zero d_deg --------
__global__ void k_scanC()
{
    __shared__ int swarp[32];
    int t = threadIdx.x, lane = t & 31, wid = t >> 5;
    int i = blockIdx.x * 1024 + t;
    int deg = (i < NN) ? d_deg[i] : 0;
    int v = deg;
#pragma unroll
    for (int o = 1; o < 32; o <<= 1) {
        int u = __shfl_up_sync(0xffffffffu, v, o);
        if (lane >= o) v += u;
    }
    if (lane == 31) swarp[wid] = v;
    __syncthreads();
    if (wid == 0) {
        int w = swarp[lane];
        int wv = w;
#pragma unroll
        for (int o = 1; o < 32; o <<= 1) {
            int u = __shfl_up_sync(0xffffffffu, wv, o);
            if (lane >= o) wv += u;
        }
        swarp[lane] = wv - w;
    }
    __syncthreads();
    if (i < NN) {
        int off = d_poff[blockIdx.x] + swarp[wid] + (v - deg);
        d_off[i] = off;
        d_cur[i] = off;
        d_dinv[i] = rsqrtf((float)(deg + 1));
        d_deg[i] = 0;
    }
}

// -------- 6: CSR fill, 4 edges/thread --------
__global__ void k_fill(const int* __restrict__ src, const int* __restrict__ dst)
{
    int base = (blockIdx.x * 256 + threadIdx.x) * 4;
    if (base < NE) {
        int4 s4 = *(const int4*)(src + base);
        int4 d4 = *(const int4*)(dst + base);
        float w0 = d_dinv[s4.x];
        float w1 = d_dinv[s4.y];
        float w2 = d_dinv[s4.z];
        float w3 = d_dinv[s4.w];
        int p0 = atomicAdd(&d_cur[d4.x], 1);
        int p1 = atomicAdd(&d_cur[d4.y], 1);
        int p2 = atomicAdd(&d_cur[d4.z], 1);
        int p3 = atomicAdd(&d_cur[d4.w], 1);
        d_csr[p0] = s4.x;  d_csrw[p0] = w0;
        d_csr[p1] = s4.y;  d_csrw[p1] = w1;
        d_csr[p2] = s4.z;  d_csrw[p2] = w2;
        d_csr[p3] = s4.w;  d_csrw[p3] = w3;
    }
}

// -------- aggregation: masked 8-batches (invalid lanes: node 0, weight 0 -> adds exact 0) --------
__global__ void __launch_bounds__(256) k_agg(const float* __restrict__ Z,
                                             const float* __restrict__ bias,
                                             float* __restrict__ H,
                                             const float* __restrict__ fcW1,
                                             int mode)
{
    int gw = (blockIdx.x * 256 + threadIdx.x) >> 5;
    int lane = threadIdx.x & 31;
    if (gw >= NN) return;
    int n = gw;
    int beg = d_off[n], end = d_off[n + 1];
    float dv = d_dinv[n];

    float2 z = *(const float2*)(Z + (size_t)n * 64 + 2 * lane);
    float ax = dv * z.x, ay = dv * z.y;

    for (int base = beg; base < end; base += 32) {
        int k = base + lane;
        int   sv = (k < end) ? d_csr[k]  : 0;
        float wv = (k < end) ? d_csrw[k] : 0.f;
        int cnt = end - base; if (cnt > 32) cnt = 32;
        for (int j = 0; j < cnt; j += 8) {
            float2 v[8];
            float  w[8];
#pragma unroll
            for (int i = 0; i < 8; i++) {
                int s = __shfl_sync(0xffffffffu, sv, j + i);
                w[i]  = __shfl_sync(0xffffffffu, wv, j + i);
                v[i]  = *(const float2*)(Z + (size_t)s * 64 + 2 * lane);
            }
#pragma unroll
            for (int i = 0; i < 8; i++) {
                ax = fmaf(w[i], v[i].x, ax);
                ay = fmaf(w[i], v[i].y, ay);
            }
        }
    }

    float2 bb = *(const float2*)(bias + 2 * lane);
    float hx = fmaf(dv, ax, bb.x);
    float hy = fmaf(dv, ay, bb.y);

    if (mode == 0) {
        hx = fmaxf(hx, 0.f);
        hy = fmaxf(hy, 0.f);
        *(float2*)(H + (size_t)n * 64 + 2 * lane) = make_float2(hx, hy);
    } else {
        float4 w = *(const float4*)(fcW1 + 4 * lane);
        float g0 = fmaf(hx, w.x, hy * w.z);
        float g1 = fmaf(hx, w.y, hy * w.w);
#pragma unroll
        for (int o = 16; o > 0; o >>= 1) {
            g0 += __shfl_xor_sync(0xffffffffu, g0, o);
            g1 += __shfl_xor_sync(0xffffffffu, g1, o);
        }
        if (lane == 0) d_g[n] = make_float2(g0, g1);
    }
}

// -------- edge head: 4 edges/thread (reads harness pointers, round-4 verbatim) --------
__global__ void __launch_bounds__(256) k_edge(const int* __restrict__ src,
                                              const int* __restrict__ dst,
                                              const int* __restrict__ attr,
                                              float4* __restrict__ out)
{
    __shared__ float Cs[92];
    if (threadIdx.x < 92) Cs[threadIdx.x] = d_C[threadIdx.x];
    __syncthreads();

    int base = (blockIdx.x * 256 + threadIdx.x) * 4;
    if (base >= NE) return;

    int4 s4 = *(const int4*)(src + base);
    int4 d4 = *(const int4*)(dst + base);
    int4 a0 = *(const int4*)(attr + base);
    int4 a1 = *(const int4*)(attr + NE + base);
    int4 a2 = *(const int4*)(attr + 2 * NE + base);
    int4 a3 = *(const int4*)(attr + 3 * NE + base);

    float2 gss[4] = {d_g[s4.x], d_g[s4.y], d_g[s4.z], d_g[s4.w]};
    float2 gdd[4] = {d_g[d4.x], d_g[d4.y], d_g[d4.z], d_g[d4.w]};
    int aa0[4] = {a0.x, a0.y, a0.z, a0.w};
    int aa1[4] = {a1.x, a1.y, a1.z, a1.w};
    int aa2[4] = {a2.x, a2.y, a2.z, a2.w};
    int aa3[4] = {a3.x, a3.y, a3.z, a3.w};

    float r[8];
#pragma unroll
    for (int i = 0; i < 4; i++) {
        float f0 = (float)aa0[i], f1 = (float)aa1[i];
        float u0 = gss[i].x - gdd[i].x + f0 * Cs[80] + f1 * Cs[82]
                 + Cs[aa2[i] * 2]     + Cs[40 + aa3[i] * 2]     + Cs[84];
        float u1 = gss[i].y - gdd[i].y + f0 * Cs[81] + f1 * Cs[83]
                 + Cs[aa2[i] * 2 + 1] + Cs[40 + aa3[i] * 2 + 1] + Cs[85];
        u0 = fmaxf(u0, 0.f);
        u1 = fmaxf(u1, 0.f);
        float v0 = u0 * Cs[86] + u1 * Cs[88] + Cs[90];
        float v1 = u0 * Cs[87] + u1 * Cs[89] + Cs[91];
        float m = fmaxf(v0, v1);
        float lse = m + __logf(__expf(v0 - m) + __expf(v1 - m));
        r[i * 2]     = v0 - lse;
        r[i * 2 + 1] = v1 - lse;
    }

    out[base >> 1]       = make_float4(r[0], r[1], r[2], r[3]);
    out[(base >> 1) + 1] = make_float4(r[4], r[5], r[6], r[7]);
}

extern "C" void kernel_launch(void* const* d_in, const int* in_sizes, int n_in,
                              void* d_out, int out_size)
{
    const float* x    = (const float*)d_in[0];
    const int*   ei   = (const int*)  d_in[1];
    const int*   ea   = (const int*)  d_in[2];
    const float* W1   = (const float*)d_in[3];
    const float* b1   = (const float*)d_in[4];
    const float* W2   = (const float*)d_in[5];
    const float* b2   = (const float*)d_in[6];
    const float* emb0 = (const float*)d_in[7];
    const float* emb1 = (const float*)d_in[8];
    const float* fcW1 = (const float*)d_in[9];
    const float* fcb1 = (const float*)d_in[10];
    const float* fcW2 = (const float*)d_in[11];
    const float* fcb2 = (const float*)d_in[12];

    const int* src = ei;
    const int* dst = ei + NE;

    int gbX  = (NN * 16 + 255) / 256;
    int gbE4 = (NE / 4 + 255) / 256;
    int gbG  = (2 * NN + 255) / 256;
    int gbW  = (NN * 32 + 255) / 256;

    // Round-4 launch order, with diagnostic stage prepended (result unused).
    k_stageX<<<gbX, 256>>>((const float4*)x);                                  // 1 (dead)
    k_count<<<gbE4, 256>>>(dst);                                               // 2
    k_scanA<<<NB, 1024>>>();                                                   // 3
    k_scanB<<<1, 128>>>(emb0, emb1, fcW1, fcb1, fcW2, fcb2);                   // 4
    k_gemm <<<gbG, 256>>>(x, W1, (float*)d_bufA);                              // 5
    k_scanC<<<NB, 1024>>>();                                                   // 6
    k_fill <<<gbE4, 256>>>(src, dst);                                          // 7
    k_agg  <<<gbW, 256>>>((const float*)d_bufA, b1, (float*)d_bufB, fcW1, 0);  // 8
    k_gemm <<<gbG, 256>>>((const float*)d_bufB, W2, (float*)d_bufA);           // 9
    k_agg  <<<gbW, 256>>>((const float*)d_bufA, b2, nullptr, fcW1, 1);         // 10
    k_edge <<<gbE4, 256>>>(src, dst, ea, (float4*)d_out);                      // 11
}

// round 12
// speedup vs baseline: 13.5619x; 13.5619x over previous
#include <cuda_runtime.h>

#define NN 100000
#define NE 1600000
#define NB 98   // ceil(NN/1024)

// -------- static scratch; accessed ONLY from device code via symbol --------
__device__ int    d_deg[NN];        // invariant: zero at entry (re-zeroed by scanC)
__device__ int    d_off[NN + 1];
__device__ int    d_cur[NN];
__device__ float  d_dinv[NN];
__device__ int    d_csr[NE];
__device__ float  d_csrw[NE];
__device__ float4 d_bufA[NN * 16];
__device__ float4 d_bufB[NN * 16];
__device__ float2 d_g[NN];
__device__ float  d_C[96];
__device__ int    d_part[NB];
__device__ int    d_poff[NB];

// -------- 1: degree count, 4 edges/thread --------
__global__ void k_count(const int* __restrict__ dst)
{
    int base = (blockIdx.x * 256 + threadIdx.x) * 4;
    if (base < NE) {
        int4 d4 = *(const int4*)(dst + base);
        atomicAdd(&d_deg[d4.x], 1);
        atomicAdd(&d_deg[d4.y], 1);
        atomicAdd(&d_deg[d4.z], 1);
        atomicAdd(&d_deg[d4.w], 1);
    }
}

// -------- 2: per-1024-chunk partial sums --------
__global__ void k_scanA()
{
    __shared__ int sred[1024];
    int t = threadIdx.x;
    int i = blockIdx.x * 1024 + t;
    sred[t] = (i < NN) ? d_deg[i] : 0;
    __syncthreads();
#pragma unroll
    for (int o = 512; o > 0; o >>= 1) {
        if (t < o) sred[t] += sred[t + o];
        __syncthreads();
    }
    if (t == 0) d_part[blockIdx.x] = sred[0];
}

// -------- 3: scan the 98 partials + constant-table prep --------
__global__ void k_scanB(const float* __restrict__ emb0, const float* __restrict__ emb1,
                        const float* __restrict__ fcW1, const float* __restrict__ fcb1,
                        const float* __restrict__ fcW2, const float* __restrict__ fcb2)
{
    int t = threadIdx.x;
    if (t < 40) {
        int i = t >> 1, j = t & 1;
        float s = 0.f;
#pragma unroll
        for (int k = 0; k < 32; k++) s = fmaf(emb0[i * 32 + k], fcW1[(66 + k) * 2 + j], s);
        d_C[t] = s;
    } else if (t < 80) {
        int u = t - 40;
        int i = u >> 1, j = u & 1;
        float s = 0.f;
#pragma unroll
        for (int k = 0; k < 32; k++) s = fmaf(emb1[i * 32 + k], fcW1[(98 + k) * 2 + j], s);
        d_C[t] = s;
    } else if (t < 92) {
        int u = t - 80;
        float v;
        if (u < 4)       v = fcW1[128 + u];
        else if (u < 6)  v = fcb1[u - 4];
        else if (u < 10) v = fcW2[u - 6];
        else             v = fcb2[u - 10];
        d_C[t] = v;
    }
    if (t == 127) {
        int run = 0;
#pragma unroll 7
        for (int i = 0; i < NB; i++) { int v = d_part[i]; d_poff[i] = run; run += v; }
        d_off[NN] = run;
    }
}

// -------- GEMM core: Z(symbol d_bufA) = X @ W. 2 threads/node, prefetch 8 float4 --------
template <int SRC>   // 0: X = external arg (x). 1: X = d_bufB symbol.
__global__ void __launch_bounds__(256) k_gemm(const float* __restrict__ Xext,
                                              const float* __restrict__ W)
{
    __shared__ float Ws[4096];
    {
        const float4* W4 = (const float4*)W;
        float4* Ws4 = (float4*)Ws;
        for (int i = threadIdx.x; i < 1024; i += 256) Ws4[i] = W4[i];
    }
    __syncthreads();

    int idx = blockIdx.x * 256 + threadIdx.x;
    int n = idx >> 1, half = idx & 1;
    if (n >= NN) return;

    const float* X = (SRC == 0) ? Xext : (const float*)d_bufB;
    const float4* xr = (const float4*)(X + (size_t)n * 64);
    float acc[32];
#pragma unroll
    for (int j = 0; j < 32; j++) acc[j] = 0.f;

#pragma unroll
    for (int hblk = 0; hblk < 2; hblk++) {
        float4 xv[8];
#pragma unroll
        for (int i = 0; i < 8; i++) xv[i] = xr[hblk * 8 + i];
#pragma unroll
        for (int i = 0; i < 8; i++) {
            int k4 = hblk * 8 + i;
#pragma unroll
            for (int kk = 0; kk < 4; kk++) {
                float xs = (kk == 0) ? xv[i].x : (kk == 1) ? xv[i].y : (kk == 2) ? xv[i].z : xv[i].w;
                const float4* wr = (const float4*)(Ws + (k4 * 4 + kk) * 64 + half * 32);
#pragma unroll
                for (int j4 = 0; j4 < 8; j4++) {
                    float4 w = wr[j4];
                    acc[j4 * 4 + 0] = fmaf(xs, w.x, acc[j4 * 4 + 0]);
                    acc[j4 * 4 + 1] = fmaf(xs, w.y, acc[j4 * 4 + 1]);
                    acc[j4 * 4 + 2] = fmaf(xs, w.z, acc[j4 * 4 + 2]);
                    acc[j4 * 4 + 3] = fmaf(xs, w.w, acc[j4 * 4 + 3]);
                }
            }
        }
    }

    float4* zr = (float4*)((float*)d_bufA + (size_t)n * 64 + half * 32);
#pragma unroll
    for (int j4 = 0; j4 < 8; j4++)
        zr[j4] = make_float4(acc[j4 * 4], acc[j4 * 4 + 1], acc[j4 * 4 + 2], acc[j4 * 4 + 3]);
}

// -------- 5: offsets/cursor/dinv via block scan + re-zero d_deg --------
__global__ void k_scanC()
{
    __shared__ int swarp[32];
    int t = threadIdx.x, lane = t & 31, wid = t >> 5;
    int i = blockIdx.x * 1024 + t;
    int deg = (i < NN) ? d_deg[i] : 0;
    int v = deg;
#pragma unroll
    for (int o = 1; o < 32; o <<= 1) {
        int u = __shfl_up_sync(0xffffffffu, v, o);
        if (lane >= o) v += u;
    }
    if (lane == 31) swarp[wid] = v;
    __syncthreads();
    if (wid == 0) {
        int w = swarp[lane];
        int wv = w;
#pragma unroll
        for (int o = 1; o < 32; o <<= 1) {
            int u = __shfl_up_sync(0xffffffffu, wv, o);
            if (lane >= o) wv += u;
        }
        swarp[lane] = wv - w;
    }
    __syncthreads();
    if (i < NN) {
        int off = d_poff[blockIdx.x] + swarp[wid] + (v - deg);
        d_off[i] = off;
        d_cur[i] = off;
        d_dinv[i] = rsqrtf((float)(deg + 1));
        d_deg[i] = 0;
    }
}

// -------- 6: CSR fill, 4 edges/thread --------
__global__ void k_fill(const int* __restrict__ src, const int* __restrict__ dst)
{
    int base = (blockIdx.x * 256 + threadIdx.x) * 4;
    if (base < NE) {
        int4 s4 = *(const int4*)(src + base);
        int4 d4 = *(const int4*)(dst + base);
        float w0 = d_dinv[s4.x];
        float w1 = d_dinv[s4.y];
        float w2 = d_dinv[s4.z];
        float w3 = d_dinv[s4.w];
        int p0 = atomicAdd(&d_cur[d4.x], 1);
        int p1 = atomicAdd(&d_cur[d4.y], 1);
        int p2 = atomicAdd(&d_cur[d4.z], 1);
        int p3 = atomicAdd(&d_cur[d4.w], 1);
        d_csr[p0] = s4.x;  d_csrw[p0] = w0;
        d_csr[p1] = s4.y;  d_csrw[p1] = w1;
        d_csr[p2] = s4.z;  d_csrw[p2] = w2;
        d_csr[p3] = s4.w;  d_csrw[p3] = w3;
    }
}

// -------- aggregation: reads d_bufA symbol. MODE 0: relu -> d_bufB. MODE 1: -> d_g --------
template <int MODE>
__global__ void __launch_bounds__(256) k_agg(const float* __restrict__ bias,
                                             const float* __restrict__ fcW1)
{
    int gw = (blockIdx.x * 256 + threadIdx.x) >> 5;
    int lane = threadIdx.x & 31;
    if (gw >= NN) return;
    int n = gw;
    int beg = d_off[n], end = d_off[n + 1];
    float dv = d_dinv[n];

    const float* Z = (const float*)d_bufA;
    float2 z = *(const float2*)(Z + (size_t)n * 64 + 2 * lane);
    float ax = dv * z.x, ay = dv * z.y;

    for (int base = beg; base < end; base += 32) {
        int k = base + lane;
        int   sv = (k < end) ? d_csr[k]  : 0;
        float wv = (k < end) ? d_csrw[k] : 0.f;
        int cnt = end - base; if (cnt > 32) cnt = 32;
        for (int j = 0; j < cnt; j += 8) {
            float2 v[8];
            float  w[8];
#pragma unroll
            for (int i = 0; i < 8; i++) {
                int s = __shfl_sync(0xffffffffu, sv, j + i);
                w[i]  = __shfl_sync(0xffffffffu, wv, j + i);
                v[i]  = *(const float2*)(Z + (size_t)s * 64 + 2 * lane);
            }
#pragma unroll
            for (int i = 0; i < 8; i++) {
                ax = fmaf(w[i], v[i].x, ax);
                ay = fmaf(w[i], v[i].y, ay);
            }
        }
    }

    float2 bb = *(const float2*)(bias + 2 * lane);
    float hx = fmaf(dv, ax, bb.x);
    float hy = fmaf(dv, ay, bb.y);

    if (MODE == 0) {
        hx = fmaxf(hx, 0.f);
        hy = fmaxf(hy, 0.f);
        *(float2*)((float*)d_bufB + (size_t)n * 64 + 2 * lane) = make_float2(hx, hy);
    } else {
        float4 w = *(const float4*)(fcW1 + 4 * lane);
        float g0 = fmaf(hx, w.x, hy * w.z);
        float g1 = fmaf(hx, w.y, hy * w.w);
#pragma unroll
        for (int o = 16; o > 0; o >>= 1) {
            g0 += __shfl_xor_sync(0xffffffffu, g0, o);
            g1 += __shfl_xor_sync(0xffffffffu, g1, o);
        }
        if (lane == 0) d_g[n] = make_float2(g0, g1);
    }
}

// -------- edge head: 4 edges/thread --------
__global__ void __launch_bounds__(256) k_edge(const int* __restrict__ src,
                                              const int* __restrict__ dst,
                                              const int* __restrict__ attr,
                                              float4* __restrict__ out)
{
    __shared__ float Cs[92];
    if (threadIdx.x < 92) Cs[threadIdx.x] = d_C[threadIdx.x];
    __syncthreads();

    int base = (blockIdx.x * 256 + threadIdx.x) * 4;
    if (base >= NE) return;

    int4 s4 = *(const int4*)(src + base);
    int4 d4 = *(const int4*)(dst + base);
    int4 a0 = *(const int4*)(attr + base);
    int4 a1 = *(const int4*)(attr + NE + base);
    int4 a2 = *(const int4*)(attr + 2 * NE + base);
    int4 a3 = *(const int4*)(attr + 3 * NE + base);

    float2 gss[4] = {d_g[s4.x], d_g[s4.y], d_g[s4.z], d_g[s4.w]};
    float2 gdd[4] = {d_g[d4.x], d_g[d4.y], d_g[d4.z], d_g[d4.w]};
    int aa0[4] = {a0.x, a0.y, a0.z, a0.w};
    int aa1[4] = {a1.x, a1.y, a1.z, a1.w};
    int aa2[4] = {a2.x, a2.y, a2.z, a2.w};
    int aa3[4] = {a3.x, a3.y, a3.z, a3.w};

    float r[8];
#pragma unroll
    for (int i = 0; i < 4; i++) {
        float f0 = (float)aa0[i], f1 = (float)aa1[i];
        float u0 = gss[i].x - gdd[i].x + f0 * Cs[80] + f1 * Cs[82]
                 + Cs[aa2[i] * 2]     + Cs[40 + aa3[i] * 2]     + Cs[84];
        float u1 = gss[i].y - gdd[i].y + f0 * Cs[81] + f1 * Cs[83]
                 + Cs[aa2[i] * 2 + 1] + Cs[40 + aa3[i] * 2 + 1] + Cs[85];
        u0 = fmaxf(u0, 0.f);
        u1 = fmaxf(u1, 0.f);
        float v0 = u0 * Cs[86] + u1 * Cs[88] + Cs[90];
        float v1 = u0 * Cs[87] + u1 * Cs[89] + Cs[91];
        float m = fmaxf(v0, v1);
        float lse = m + __logf(__expf(v0 - m) + __expf(v1 - m));
        r[i * 2]     = v0 - lse;
        r[i * 2 + 1] = v1 - lse;
    }

    out[base >> 1]       = make_float4(r[0], r[1], r[2], r[3]);
    out[(base >> 1) + 1] = make_float4(r[4], r[5], r[6], r[7]);
}

extern "C" void kernel_launch(void* const* d_in, const int* in_sizes, int n_in,
                              void* d_out, int out_size)
{
    const float* x    = (const float*)d_in[0];
    const int*   ei   = (const int*)  d_in[1];
    const int*   ea   = (const int*)  d_in[2];
    const float* W1   = (const float*)d_in[3];
    const float* b1   = (const float*)d_in[4];
    const float* W2   = (const float*)d_in[5];
    const float* b2   = (const float*)d_in[6];
    const float* emb0 = (const float*)d_in[7];
    const float* emb1 = (const float*)d_in[8];
    const float* fcW1 = (const float*)d_in[9];
    const float* fcb1 = (const float*)d_in[10];
    const float* fcW2 = (const float*)d_in[11];
    const float* fcb2 = (const float*)d_in[12];

    const int* src = ei;
    const int* dst = ei + NE;

    int gbE4 = (NE / 4 + 255) / 256;
    int gbG  = (2 * NN + 255) / 256;
    int gbW  = (NN * 32 + 255) / 256;

    k_count  <<<gbE4, 256>>>(dst);                                   // 1
    k_scanA  <<<NB, 1024>>>();                                       // 2
    k_scanB  <<<1, 128>>>(emb0, emb1, fcW1, fcb1, fcW2, fcb2);       // 3
    k_gemm<0><<<gbG, 256>>>(x, W1);                                  // 4  <-- ncu capture slot
    k_scanC  <<<NB, 1024>>>();                                       // 5
    k_fill   <<<gbE4, 256>>>(src, dst);                              // 6
    k_agg<0> <<<gbW, 256>>>(b1, fcW1);                               // 7
    k_gemm<1><<<gbG, 256>>>(nullptr, W2);                            // 8
    k_agg<1> <<<gbW, 256>>>(b2, fcW1);                               // 9
    k_edge   <<<gbE4, 256>>>(src, dst, ea, (float4*)d_out);          // 10
}

// round 13
// speedup vs baseline: 25.7596x; 1.8994x over previous
#include <cuda_runtime.h>

#define NN 100000
#define NE 1600000
#define NB 98   // ceil(NN/1024)

// -------- static scratch; accessed ONLY from device code via symbol --------
__device__ int    d_deg[NN];        // invariant: zero at entry (re-zeroed by scanC)
__device__ int    d_off[NN + 1];
__device__ int    d_cur[NN];
__device__ float  d_dinv[NN];
__device__ int    d_csr[NE];
__device__ float  d_csrw[NE];
__device__ float4 d_bufA[NN * 16];
__device__ float4 d_bufB[NN * 16];
__device__ float2 d_g[NN];
__device__ float  d_C[96];
__device__ int    d_part[NB];
__device__ int    d_poff[NB];

// -------- 1: degree count, 4 edges/thread --------
__global__ void k_count(const int* __restrict__ dst)
{
    int base = (blockIdx.x * 256 + threadIdx.x) * 4;
    if (base < NE) {
        int4 d4 = *(const int4*)(dst + base);
        atomicAdd(&d_deg[d4.x], 1);
        atomicAdd(&d_deg[d4.y], 1);
        atomicAdd(&d_deg[d4.z], 1);
        atomicAdd(&d_deg[d4.w], 1);
    }
}

// -------- 2: per-1024-chunk partial sums --------
__global__ void k_scanA()
{
    __shared__ int sred[1024];
    int t = threadIdx.x;
    int i = blockIdx.x * 1024 + t;
    sred[t] = (i < NN) ? d_deg[i] : 0;
    __syncthreads();
#pragma unroll
    for (int o = 512; o > 0; o >>= 1) {
        if (t < o) sred[t] += sred[t + o];
        __syncthreads();
    }
    if (t == 0) d_part[blockIdx.x] = sred[0];
}

// -------- 3: scan the 98 partials + constant-table prep --------
__global__ void k_scanB(const float* __restrict__ emb0, const float* __restrict__ emb1,
                        const float* __restrict__ fcW1, const float* __restrict__ fcb1,
                        const float* __restrict__ fcW2, const float* __restrict__ fcb2)
{
    int t = threadIdx.x;
    if (t < 40) {
        int i = t >> 1, j = t & 1;
        float s = 0.f;
#pragma unroll
        for (int k = 0; k < 32; k++) s = fmaf(emb0[i * 32 + k], fcW1[(66 + k) * 2 + j], s);
        d_C[t] = s;
    } else if (t < 80) {
        int u = t - 40;
        int i = u >> 1, j = u & 1;
        float s = 0.f;
#pragma unroll
        for (int k = 0; k < 32; k++) s = fmaf(emb1[i * 32 + k], fcW1[(98 + k) * 2 + j], s);
        d_C[t] = s;
    } else if (t < 92) {
        int u = t - 80;
        float v;
        if (u < 4)       v = fcW1[128 + u];
        else if (u < 6)  v = fcb1[u - 4];
        else if (u < 10) v = fcW2[u - 6];
        else             v = fcb2[u - 10];
        d_C[t] = v;
    }
    if (t == 127) {
        int run = 0;
#pragma unroll 7
        for (int i = 0; i < NB; i++) { int v = d_part[i]; d_poff[i] = run; run += v; }
        d_off[NN] = run;
    }
}

// -------- GEMM: d_bufA = X @ W. Register-blocked 4x8 per thread, 64-node tile --------
// 128 threads/block: tx = t&7 (8 col-groups of 8), ty = t>>3 (16 node-groups of 4).
template <int SRC>   // 0: X = external arg. 1: X = d_bufB symbol.
__global__ void __launch_bounds__(128) k_gemm(const float* __restrict__ Xext,
                                              const float* __restrict__ W)
{
    __shared__ float Xs[64 * 68];   // node-major, padded row (aligned float4 stores)
    __shared__ float Ws[64 * 64];   // k-major

    const float* X = (SRC == 0) ? Xext : (const float*)d_bufB;
    int t = threadIdx.x;
    int n0 = blockIdx.x * 64;

    // load W: 1024 float4 over 128 threads
    {
        const float4* W4 = (const float4*)W;
        float4* Ws4 = (float4*)Ws;
#pragma unroll
        for (int i = 0; i < 8; i++) Ws4[t + i * 128] = W4[t + i * 128];
    }
    // load X tile: 64 rows x 16 float4
    {
        const float4* Xg = (const float4*)(X + (size_t)n0 * 64);
#pragma unroll
        for (int i = 0; i < 8; i++) {
            int f = t + i * 128;
            int row = f >> 4, c4 = f & 15;
            float4 v = (n0 + row < NN) ? Xg[f] : make_float4(0.f, 0.f, 0.f, 0.f);
            *(float4*)(Xs + row * 68 + c4 * 4) = v;
        }
    }
    __syncthreads();

    int tx = t & 7;
    int ty = t >> 3;
    int tn = tx * 8;
    int tm = ty * 4;

    float acc[4][8];
#pragma unroll
    for (int i = 0; i < 4; i++)
#pragma unroll
        for (int j = 0; j < 8; j++) acc[i][j] = 0.f;

#pragma unroll 8
    for (int k = 0; k < 64; k++) {
        float xv0 = Xs[(tm + 0) * 68 + k];
        float xv1 = Xs[(tm + 1) * 68 + k];
        float xv2 = Xs[(tm + 2) * 68 + k];
        float xv3 = Xs[(tm + 3) * 68 + k];
        float4 wa = *(const float4*)(Ws + k * 64 + tn);
        float4 wb = *(const float4*)(Ws + k * 64 + tn + 4);

        acc[0][0] = fmaf(xv0, wa.x, acc[0][0]); acc[0][1] = fmaf(xv0, wa.y, acc[0][1]);
        acc[0][2] = fmaf(xv0, wa.z, acc[0][2]); acc[0][3] = fmaf(xv0, wa.w, acc[0][3]);
        acc[0][4] = fmaf(xv0, wb.x, acc[0][4]); acc[0][5] = fmaf(xv0, wb.y, acc[0][5]);
        acc[0][6] = fmaf(xv0, wb.z, acc[0][6]); acc[0][7] = fmaf(xv0, wb.w, acc[0][7]);

        acc[1][0] = fmaf(xv1, wa.x, acc[1][0]); acc[1][1] = fmaf(xv1, wa.y, acc[1][1]);
        acc[1][2] = fmaf(xv1, wa.z, acc[1][2]); acc[1][3] = fmaf(xv1, wa.w, acc[1][3]);
        acc[1][4] = fmaf(xv1, wb.x, acc[1][4]); acc[1][5] = fmaf(xv1, wb.y, acc[1][5]);
        acc[1][6] = fmaf(xv1, wb.z, acc[1][6]); acc[1][7] = fmaf(xv1, wb.w, acc[1][7]);

        acc[2][0] = fmaf(xv2, wa.x, acc[2][0]); acc[2][1] = fmaf(xv2, wa.y, acc[2][1]);
        acc[2][2] = fmaf(xv2, wa.z, acc[2][2]); acc[2][3] = fmaf(xv2, wa.w, acc[2][3]);
        acc[2][4] = fmaf(xv2, wb.x, acc[2][4]); acc[2][5] = fmaf(xv2, wb.y, acc[2][5]);
        acc[2][6] = fmaf(xv2, wb.z, acc[2][6]); acc[2][7] = fmaf(xv2, wb.w, acc[2][7]);

        acc[3][0] = fmaf(xv3, wa.x, acc[3][0]); acc[3][1] = fmaf(xv3, wa.y, acc[3][1]);
        acc[3][2] = fmaf(xv3, wa.z, acc[3][2]); acc[3][3] = fmaf(xv3, wa.w, acc[3][3]);
        acc[3][4] = fmaf(xv3, wb.x, acc[3][4]); acc[3][5] = fmaf(xv3, wb.y, acc[3][5]);
        acc[3][6] = fmaf(xv3, wb.z, acc[3][6]); acc[3][7] = fmaf(xv3, wb.w, acc[3][7]);
    }

#pragma unroll
    for (int i = 0; i < 4; i++) {
        int n = n0 + tm + i;
        if (n < NN) {
            float4* zr = (float4*)((float*)d_bufA + (size_t)n * 64 + tn);
            zr[0] = make_float4(acc[i][0], acc[i][1], acc[i][2], acc[i][3]);
            zr[1] = make_float4(acc[i][4], acc[i][5], acc[i][6], acc[i][7]);
        }
    }
}

// -------- 5: offsets/cursor/dinv via block scan + re-zero d_deg --------
__global__ void k_scanC()
{
    __shared__ int swarp[32];
    int t = threadIdx.x, lane = t & 31, wid = t >> 5;
    int i = blockIdx.x * 1024 + t;
    int deg = (i < NN) ? d_deg[i] : 0;
    int v = deg;
#pragma unroll
    for (int o = 1; o < 32; o <<= 1) {
        int u = __shfl_up_sync(0xffffffffu, v, o);
        if (lane >= o) v += u;
    }
    if (lane == 31) swarp[wid] = v;
    __syncthreads();
    if (wid == 0) {
        int w = swarp[lane];
        int wv = w;
#pragma unroll
        for (int o = 1; o < 32; o <<= 1) {
            int u = __shfl_up_sync(0xffffffffu, wv, o);
            if (lane >= o) wv += u;
        }
        swarp[lane] = wv - w;
    }
    __syncthreads();
    if (i < NN) {
        int off = d_poff[blockIdx.x] + swarp[wid] + (v - deg);
        d_off[i] = off;
        d_cur[i] = off;
        d_dinv[i] = rsqrtf((float)(deg + 1));
        d_deg[i] = 0;
    }
}

// -------- 6: CSR fill, 4 edges/thread --------
__global__ void k_fill(const int* __restrict__ src, const int* __restrict__ dst)
{
    int base = (blockIdx.x * 256 + threadIdx.x) * 4;
    if (base < NE) {
        int4 s4 = *(const int4*)(src + base);
        int4 d4 = *(const int4*)(dst + base);
        float w0 = d_dinv[s4.x];
        float w1 = d_dinv[s4.y];
        float w2 = d_dinv[s4.z];
        float w3 = d_dinv[s4.w];
        int p0 = atomicAdd(&d_cur[d4.x], 1);
        int p1 = atomicAdd(&d_cur[d4.y], 1);
        int p2 = atomicAdd(&d_cur[d4.z], 1);
        int p3 = atomicAdd(&d_cur[d4.w], 1);
        d_csr[p0] = s4.x;  d_csrw[p0] = w0;
        d_csr[p1] = s4.y;  d_csrw[p1] = w1;
        d_csr[p2] = s4.z;  d_csrw[p2] = w2;
        d_csr[p3] = s4.w;  d_csrw[p3] = w3;
    }
}

// -------- aggregation: reads d_bufA symbol. MODE 0: relu -> d_bufB. MODE 1: -> d_g --------
template <int MODE>
__global__ void __launch_bounds__(256) k_agg(const float* __restrict__ bias,
                                             const float* __restrict__ fcW1)
{
    int gw = (blockIdx.x * 256 + threadIdx.x) >> 5;
    int lane = threadIdx.x & 31;
    if (gw >= NN) return;
    int n = gw;
    int beg = d_off[n], end = d_off[n + 1];
    float dv = d_dinv[n];

    const float* Z = (const float*)d_bufA;
    float2 z = *(const float2*)(Z + (size_t)n * 64 + 2 * lane);
    float ax = dv * z.x, ay = dv * z.y;

    for (int base = beg; base < end; base += 32) {
        int k = base + lane;
        int   sv = (k < end) ? d_csr[k]  : 0;
        float wv = (k < end) ? d_csrw[k] : 0.f;
        int cnt = end - base; if (cnt > 32) cnt = 32;
        for (int j = 0; j < cnt; j += 8) {
            float2 v[8];
            float  w[8];
#pragma unroll
            for (int i = 0; i < 8; i++) {
                int s = __shfl_sync(0xffffffffu, sv, j + i);
                w[i]  = __shfl_sync(0xffffffffu, wv, j + i);
                v[i]  = *(const float2*)(Z + (size_t)s * 64 + 2 * lane);
            }
#pragma unroll
            for (int i = 0; i < 8; i++) {
                ax = fmaf(w[i], v[i].x, ax);
                ay = fmaf(w[i], v[i].y, ay);
            }
        }
    }

    float2 bb = *(const float2*)(bias + 2 * lane);
    float hx = fmaf(dv, ax, bb.x);
    float hy = fmaf(dv, ay, bb.y);

    if (MODE == 0) {
        hx = fmaxf(hx, 0.f);
        hy = fmaxf(hy, 0.f);
        *(float2*)((float*)d_bufB + (size_t)n * 64 + 2 * lane) = make_float2(hx, hy);
    } else {
        float4 w = *(const float4*)(fcW1 + 4 * lane);
        float g0 = fmaf(hx, w.x, hy * w.z);
        float g1 = fmaf(hx, w.y, hy * w.w);
#pragma unroll
        for (int o = 16; o > 0; o >>= 1) {
            g0 += __shfl_xor_sync(0xffffffffu, g0, o);
            g1 += __shfl_xor_sync(0xffffffffu, g1, o);
        }
        if (lane == 0) d_g[n] = make_float2(g0, g1);
    }
}

// -------- edge head: 4 edges/thread --------
__global__ void __launch_bounds__(256) k_edge(const int* __restrict__ src,
                                              const int* __restrict__ dst,
                                              const int* __restrict__ attr,
                                              float4* __restrict__ out)
{
    __shared__ float Cs[92];
    if (threadIdx.x < 92) Cs[threadIdx.x] = d_C[threadIdx.x];
    __syncthreads();

    int base = (blockIdx.x * 256 + threadIdx.x) * 4;
    if (base >= NE) return;

    int4 s4 = *(const int4*)(src + base);
    int4 d4 = *(const int4*)(dst + base);
    int4 a0 = *(const int4*)(attr + base);
    int4 a1 = *(const int4*)(attr + NE + base);
    int4 a2 = *(const int4*)(attr + 2 * NE + base);
    int4 a3 = *(const int4*)(attr + 3 * NE + base);

    float2 gss[4] = {d_g[s4.x], d_g[s4.y], d_g[s4.z], d_g[s4.w]};
    float2 gdd[4] = {d_g[d4.x], d_g[d4.y], d_g[d4.z], d_g[d4.w]};
    int aa0[4] = {a0.x, a0.y, a0.z, a0.w};
    int aa1[4] = {a1.x, a1.y, a1.z, a1.w};
    int aa2[4] = {a2.x, a2.y, a2.z, a2.w};
    int aa3[4] = {a3.x, a3.y, a3.z, a3.w};

    float r[8];
#pragma unroll
    for (int i = 0; i < 4; i++) {
        float f0 = (float)aa0[i], f1 = (float)aa1[i];
        float u0 = gss[i].x - gdd[i].x + f0 * Cs[80] + f1 * Cs[82]
                 + Cs[aa2[i] * 2]     + Cs[40 + aa3[i] * 2]     + Cs[84];
        float u1 = gss[i].y - gdd[i].y + f0 * Cs[81] + f1 * Cs[83]
                 + Cs[aa2[i] * 2 + 1] + Cs[40 + aa3[i] * 2 + 1] + Cs[85];
        u0 = fmaxf(u0, 0.f);
        u1 = fmaxf(u1, 0.f);
        float v0 = u0 * Cs[86] + u1 * Cs[88] + Cs[90];
        float v1 = u0 * Cs[87] + u1 * Cs[89] + Cs[91];
        float m = fmaxf(v0, v1);
        float lse = m + __logf(__expf(v0 - m) + __expf(v1 - m));
        r[i * 2]     = v0 - lse;
        r[i * 2 + 1] = v1 - lse;
    }

    out[base >> 1]       = make_float4(r[0], r[1], r[2], r[3]);
    out[(base >> 1) + 1] = make_float4(r[4], r[5], r[6], r[7]);
}

extern "C" void kernel_launch(void* const* d_in, const int* in_sizes, int n_in,
                              void* d_out, int out_size)
{
    const float* x    = (const float*)d_in[0];
    const int*   ei   = (const int*)  d_in[1];
    const int*   ea   = (const int*)  d_in[2];
    const float* W1   = (const float*)d_in[3];
    const float* b1   = (const float*)d_in[4];
    const float* W2   = (const float*)d_in[5];
    const float* b2   = (const float*)d_in[6];
    const float* emb0 = (const float*)d_in[7];
    const float* emb1 = (const float*)d_in[8];
    const float* fcW1 = (const float*)d_in[9];
    const float* fcb1 = (const float*)d_in[10];
    const float* fcW2 = (const float*)d_in[11];
    const float* fcb2 = (const float*)d_in[12];

    const int* src = ei;
    const int* dst = ei + NE;

    int gbE4 = (NE / 4 + 255) / 256;
    int gbG  = (NN + 63) / 64;
    int gbW  = (NN * 32 + 255) / 256;

    k_count  <<<gbE4, 256>>>(dst);                                   // 1
    k_scanA  <<<NB, 1024>>>();                                       // 2
    k_scanB  <<<1, 128>>>(emb0, emb1, fcW1, fcb1, fcW2, fcb2);       // 3
    k_gemm<0><<<gbG, 128>>>(x, W1);                                  // 4  <-- ncu capture slot
    k_scanC  <<<NB, 1024>>>();                                       // 5
    k_fill   <<<gbE4, 256>>>(src, dst);                              // 6
    k_agg<0> <<<gbW, 256>>>(b1, fcW1);                               // 7
    k_gemm<1><<<gbG, 128>>>(nullptr, W2);                            // 8
    k_agg<1> <<<gbW, 256>>>(b2, fcW1);                               // 9
    k_edge   <<<gbE4, 256>>>(src, dst, ea, (float4*)d_out);          // 10
}

// round 15
// speedup vs baseline: 27.8554x; 1.0814x over previous
#include <cuda_runtime.h>

#define NN 100000
#define NE 1600000
#define NB 98   // ceil(NN/1024)

// -------- static scratch; accessed ONLY from device code via symbol --------
__device__ int    d_deg[NN];        // invariant: zero at entry (re-zeroed by scanC)
__device__ int    d_off[NN + 1];
__device__ int    d_cur[NN];
__device__ float  d_dinv[NN];
__device__ int    d_csr[NE];
__device__ float  d_csrw[NE];
__device__ float4 d_bufA[NN * 16];
__device__ float4 d_bufB[NN * 16];
__device__ float2 d_g[NN];
__device__ float  d_C[96];
__device__ int    d_part[NB];

// -------- 1: degree count, 4 edges/thread; block 0 also preps const table --------
__global__ void k_count(const int* __restrict__ dst,
                        const float* __restrict__ emb0, const float* __restrict__ emb1,
                        const float* __restrict__ fcW1, const float* __restrict__ fcb1,
                        const float* __restrict__ fcW2, const float* __restrict__ fcb2)
{
    int t = threadIdx.x;
    if (blockIdx.x == 0) {
        if (t < 40) {
            int i = t >> 1, j = t & 1;
            float s = 0.f;
#pragma unroll
            for (int k = 0; k < 32; k++) s = fmaf(emb0[i * 32 + k], fcW1[(66 + k) * 2 + j], s);
            d_C[t] = s;
        } else if (t < 80) {
            int u = t - 40;
            int i = u >> 1, j = u & 1;
            float s = 0.f;
#pragma unroll
            for (int k = 0; k < 32; k++) s = fmaf(emb1[i * 32 + k], fcW1[(98 + k) * 2 + j], s);
            d_C[t] = s;
        } else if (t < 92) {
            int u = t - 80;
            float v;
            if (u < 4)       v = fcW1[128 + u];
            else if (u < 6)  v = fcb1[u - 4];
            else if (u < 10) v = fcW2[u - 6];
            else             v = fcb2[u - 10];
            d_C[t] = v;
        }
    }
    int base = (blockIdx.x * 256 + t) * 4;
    if (base < NE) {
        int4 d4 = *(const int4*)(dst + base);
        atomicAdd(&d_deg[d4.x], 1);
        atomicAdd(&d_deg[d4.y], 1);
        atomicAdd(&d_deg[d4.z], 1);
        atomicAdd(&d_deg[d4.w], 1);
    }
}

// -------- 2: per-1024-chunk partial sums --------
__global__ void k_scanA()
{
    __shared__ int sred[1024];
    int t = threadIdx.x;
    int i = blockIdx.x * 1024 + t;
    sred[t] = (i < NN) ? d_deg[i] : 0;
    __syncthreads();
#pragma unroll
    for (int o = 512; o > 0; o >>= 1) {
        if (t < o) sred[t] += sred[t + o];
        __syncthreads();
    }
    if (t == 0) d_part[blockIdx.x] = sred[0];
}

// -------- 3: offsets/cursor/dinv; block computes own chunk prefix; re-zero d_deg --------
__global__ void k_scanC()
{
    __shared__ int swarp[32];
    __shared__ int sbase;
    int t = threadIdx.x, lane = t & 31, wid = t >> 5;
    int bid = blockIdx.x;

    if (t == 0) {
        int run = 0;
        for (int j = 0; j < bid; j++) run += d_part[j];
        sbase = run;
        if (bid == 0) d_off[NN] = NE;   // total degree == edge count
    }

    int i = bid * 1024 + t;
    int deg = (i < NN) ? d_deg[i] : 0;
    int v = deg;
#pragma unroll
    for (int o = 1; o < 32; o <<= 1) {
        int u = __shfl_up_sync(0xffffffffu, v, o);
        if (lane >= o) v += u;
    }
    if (lane == 31) swarp[wid] = v;
    __syncthreads();
    if (wid == 0) {
        int w = swarp[lane];
        int wv = w;
#pragma unroll
        for (int o = 1; o < 32; o <<= 1) {
            int u = __shfl_up_sync(0xffffffffu, wv, o);
            if (lane >= o) wv += u;
        }
        swarp[lane] = wv - w;
    }
    __syncthreads();
    if (i < NN) {
        int off = sbase + swarp[wid] + (v - deg);
        d_off[i] = off;
        d_cur[i] = off;
        d_dinv[i] = rsqrtf((float)(deg + 1));
        d_deg[i] = 0;
    }
}

// -------- GEMM: d_bufA = X @ W. 8x8 per thread, 128-node tile, 128 threads --------
template <int SRC>   // 0: X = external arg. 1: X = d_bufB symbol.
__global__ void __launch_bounds__(128) k_gemm(const float* __restrict__ Xext,
                                              const float* __restrict__ W)
{
    __shared__ float Xs[128 * 68];  // node-major, padded row
    __shared__ float Ws[64 * 64];   // k-major

    const float* X = (SRC == 0) ? Xext : (const float*)d_bufB;
    int t = threadIdx.x;
    int n0 = blockIdx.x * 128;

    // load W: 1024 float4 over 128 threads
    {
        const float4* W4 = (const float4*)W;
        float4* Ws4 = (float4*)Ws;
#pragma unroll
        for (int i = 0; i < 8; i++) Ws4[t + i * 128] = W4[t + i * 128];
    }
    // load X tile: 128 rows x 16 float4
    {
        const float4* Xg = (const float4*)(X + (size_t)n0 * 64);
#pragma unroll
        for (int i = 0; i < 16; i++) {
            int f = t + i * 128;
            int row = f >> 4, c4 = f & 15;
            float4 v = (n0 + row < NN) ? Xg[f] : make_float4(0.f, 0.f, 0.f, 0.f);
            *(float4*)(Xs + row * 68 + c4 * 4) = v;
        }
    }
    __syncthreads();

    int tx = t & 7;          // 8 col groups of 8
    int ty = t >> 3;         // 16 row groups of 8
    int tn = tx * 8;
    int tm = ty * 8;

    float acc[8][8];
#pragma unroll
    for (int i = 0; i < 8; i++)
#pragma unroll
        for (int j = 0; j < 8; j++) acc[i][j] = 0.f;

#pragma unroll 4
    for (int k = 0; k < 64; k++) {
        float4 wa = *(const float4*)(Ws + k * 64 + tn);
        float4 wb = *(const float4*)(Ws + k * 64 + tn + 4);
        float xv[8];
#pragma unroll
        for (int i = 0; i < 8; i++) xv[i] = Xs[(tm + i) * 68 + k];
#pragma unroll
        for (int i = 0; i < 8; i++) {
            acc[i][0] = fmaf(xv[i], wa.x, acc[i][0]);
            acc[i][1] = fmaf(xv[i], wa.y, acc[i][1]);
            acc[i][2] = fmaf(xv[i], wa.z, acc[i][2]);
            acc[i][3] = fmaf(xv[i], wa.w, acc[i][3]);
            acc[i][4] = fmaf(xv[i], wb.x, acc[i][4]);
            acc[i][5] = fmaf(xv[i], wb.y, acc[i][5]);
            acc[i][6] = fmaf(xv[i], wb.z, acc[i][6]);
            acc[i][7] = fmaf(xv[i], wb.w, acc[i][7]);
        }
    }

#pragma unroll
    for (int i = 0; i < 8; i++) {
        int n = n0 + tm + i;
        if (n < NN) {
            float4* zr = (float4*)((float*)d_bufA + (size_t)n * 64 + tn);
            zr[0] = make_float4(acc[i][0], acc[i][1], acc[i][2], acc[i][3]);
            zr[1] = make_float4(acc[i][4], acc[i][5], acc[i][6], acc[i][7]);
        }
    }
}

// -------- 6: CSR fill, 4 edges/thread --------
__global__ void k_fill(const int* __restrict__ src, const int* __restrict__ dst)
{
    int base = (blockIdx.x * 256 + threadIdx.x) * 4;
    if (base < NE) {
        int4 s4 = *(const int4*)(src + base);
        int4 d4 = *(const int4*)(dst + base);
        float w0 = d_dinv[s4.x];
        float w1 = d_dinv[s4.y];
        float w2 = d_dinv[s4.z];
        float w3 = d_dinv[s4.w];
        int p0 = atomicAdd(&d_cur[d4.x], 1);
        int p1 = atomicAdd(&d_cur[d4.y], 1);
        int p2 = atomicAdd(&d_cur[d4.z], 1);
        int p3 = atomicAdd(&d_cur[d4.w], 1);
        d_csr[p0] = s4.x;  d_csrw[p0] = w0;
        d_csr[p1] = s4.y;  d_csrw[p1] = w1;
        d_csr[p2] = s4.z;  d_csrw[p2] = w2;
        d_csr[p3] = s4.w;  d_csrw[p3] = w3;
    }
}

// -------- aggregation: reads d_bufA symbol. MODE 0: relu -> d_bufB. MODE 1: -> d_g --------
template <int MODE>
__global__ void __launch_bounds__(256) k_agg(const float* __restrict__ bias,
                                             const float* __restrict__ fcW1)
{
    int gw = (blockIdx.x * 256 + threadIdx.x) >> 5;
    int lane = threadIdx.x & 31;
    if (gw >= NN) return;
    int n = gw;
    int beg = d_off[n], end = d_off[n + 1];
    float dv = d_dinv[n];

    const float* Z = (const float*)d_bufA;
    float2 z = *(const float2*)(Z + (size_t)n * 64 + 2 * lane);
    float ax = dv * z.x, ay = dv * z.y;

    for (int base = beg; base < end; base += 32) {
        int k = base + lane;
        int   sv = (k < end) ? d_csr[k]  : 0;
        float wv = (k < end) ? d_csrw[k] : 0.f;
        int cnt = end - base; if (cnt > 32) cnt = 32;
        for (int j = 0; j < cnt; j += 8) {
            float2 v[8];
            float  w[8];
#pragma unroll
            for (int i = 0; i < 8; i++) {
                int s = __shfl_sync(0xffffffffu, sv, j + i);
                w[i]  = __shfl_sync(0xffffffffu, wv, j + i);
                v[i]  = *(const float2*)(Z + (size_t)s * 64 + 2 * lane);
            }
#pragma unroll
            for (int i = 0; i < 8; i++) {
                ax = fmaf(w[i], v[i].x, ax);
                ay = fmaf(w[i], v[i].y, ay);
            }
        }
    }

    float2 bb = *(const float2*)(bias + 2 * lane);
    float hx = fmaf(dv, ax, bb.x);
    float hy = fmaf(dv, ay, bb.y);

    if (MODE == 0) {
        hx = fmaxf(hx, 0.f);
        hy = fmaxf(hy, 0.f);
        *(float2*)((float*)d_bufB + (size_t)n * 64 + 2 * lane) = make_float2(hx, hy);
    } else {
        float4 w = *(const float4*)(fcW1 + 4 * lane);
        float g0 = fmaf(hx, w.x, hy * w.z);
        float g1 = fmaf(hx, w.y, hy * w.w);
#pragma unroll
        for (int o = 16; o > 0; o >>= 1) {
            g0 += __shfl_xor_sync(0xffffffffu, g0, o);
            g1 += __shfl_xor_sync(0xffffffffu, g1, o);
        }
        if (lane == 0) d_g[n] = make_float2(g0, g1);
    }
}

// -------- edge head: 4 edges/thread --------
__global__ void __launch_bounds__(256) k_edge(const int* __restrict__ src,
                                              const int* __restrict__ dst,
                                              const int* __restrict__ attr,
                                              float4* __restrict__ out)
{
    __shared__ float Cs[92];
    if (threadIdx.x < 92) Cs[threadIdx.x] = d_C[threadIdx.x];
    __syncthreads();

    int base = (blockIdx.x * 256 + threadIdx.x) * 4;
    if (base >= NE) return;

    int4 s4 = *(const int4*)(src + base);
    int4 d4 = *(const int4*)(dst + base);
    int4 a0 = *(const int4*)(attr + base);
    int4 a1 = *(const int4*)(attr + NE + base);
    int4 a2 = *(const int4*)(attr + 2 * NE + base);
    int4 a3 = *(const int4*)(attr + 3 * NE + base);

    float2 gss[4] = {d_g[s4.x], d_g[s4.y], d_g[s4.z], d_g[s4.w]};
    float2 gdd[4] = {d_g[d4.x], d_g[d4.y], d_g[d4.z], d_g[d4.w]};
    int aa0[4] = {a0.x, a0.y, a0.z, a0.w};
    int aa1[4] = {a1.x, a1.y, a1.z, a1.w};
    int aa2[4] = {a2.x, a2.y, a2.z, a2.w};
    int aa3[4] = {a3.x, a3.y, a3.z, a3.w};

    float r[8];
#pragma unroll
    for (int i = 0; i < 4; i++) {
        float f0 = (float)aa0[i], f1 = (float)aa1[i];
        float u0 = gss[i].x - gdd[i].x + f0 * Cs[80] + f1 * Cs[82]
                 + Cs[aa2[i] * 2]     + Cs[40 + aa3[i] * 2]     + Cs[84];
        float u1 = gss[i].y - gdd[i].y + f0 * Cs[81] + f1 * Cs[83]
                 + Cs[aa2[i] * 2 + 1] + Cs[40 + aa3[i] * 2 + 1] + Cs[85];
        u0 = fmaxf(u0, 0.f);
        u1 = fmaxf(u1, 0.f);
        float v0 = u0 * Cs[86] + u1 * Cs[88] + Cs[90];
        float v1 = u0 * Cs[87] + u1 * Cs[89] + Cs[91];
        float m = fmaxf(v0, v1);
        float lse = m + __logf(__expf(v0 - m) + __expf(v1 - m));
        r[i * 2]     = v0 - lse;
        r[i * 2 + 1] = v1 - lse;
    }

    out[base >> 1]       = make_float4(r[0], r[1], r[2], r[3]);
    out[(base >> 1) + 1] = make_float4(r[4], r[5], r[6], r[7]);
}

extern "C" void kernel_launch(void* const* d_in, const int* in_sizes, int n_in,
                              void* d_out, int out_size)
{
    const float* x    = (const float*)d_in[0];
    const int*   ei   = (const int*)  d_in[1];
    const int*   ea   = (const int*)  d_in[2];
    const float* W1   = (const float*)d_in[3];
    const float* b1   = (const float*)d_in[4];
    const float* W2   = (const float*)d_in[5];
    const float* b2   = (const float*)d_in[6];
    const float* emb0 = (const float*)d_in[7];
    const float* emb1 = (const float*)d_in[8];
    const float* fcW1 = (const float*)d_in[9];
    const float* fcb1 = (const float*)d_in[10];
    const float* fcW2 = (const float*)d_in[11];
    const float* fcb2 = (const float*)d_in[12];

    const int* src = ei;
    const int* dst = ei + NE;

    int gbE4 = (NE / 4 + 255) / 256;
    int gbG  = (NN + 127) / 128;
    int gbW  = (NN * 32 + 255) / 256;

    k_count  <<<gbE4, 256>>>(dst, emb0, emb1, fcW1, fcb1, fcW2, fcb2);   // 1
    k_scanA  <<<NB, 1024>>>();                                           // 2
    k_scanC  <<<NB, 1024>>>();                                           // 3
    k_gemm<0><<<gbG, 128>>>(x, W1);                                      // 4  <-- ncu capture slot
    k_fill   <<<gbE4, 256>>>(src, dst);                                  // 5
    k_agg<0> <<<gbW, 256>>>(b1, fcW1);                                   // 6
    k_gemm<1><<<gbG, 128>>>(nullptr, W2);                                // 7
    k_agg<1> <<<gbW, 256>>>(b2, fcW1);                                   // 8
    k_edge   <<<gbE4, 256>>>(src, dst, ea, (float4*)d_out);              // 9
}

// round 16
// speedup vs baseline: 38.4629x; 1.3808x over previous
#include <cuda_runtime.h>

#define NN 100000
#define NE 1600000
#define NB 98   // ceil(NN/1024)

// -------- static scratch; accessed ONLY from device code via symbol --------
__device__ int    d_deg[NN];        // invariant: zero at entry (re-zeroed by scanC)
__device__ int    d_off[NN + 1];
__device__ int    d_cur[NN];
__device__ float  d_dinv[NN];
__device__ int    d_csr[NE];
__device__ float  d_csrw[NE];
__device__ float4 d_bufA[NN * 16];  // Z1 = x @ W1
__device__ float2 d_q[NN];          // q[n] = relu-h1[n] @ (W2 @ P)
__device__ float2 d_g[NN];
__device__ float  d_C[96];          // [0..39] P0, [40..79] P1, [80..91] scalars, [92..93] b2@P
__device__ float  d_W2P[128];       // (W2 @ fcW1[0:64,0:2]) row-major [k][j]
__device__ int    d_part[NB];

// -------- 1: degree count, 4 edges/thread; block 0 also preps const tables --------
__global__ void k_count(const int* __restrict__ dst,
                        const float* __restrict__ emb0, const float* __restrict__ emb1,
                        const float* __restrict__ fcW1, const float* __restrict__ fcb1,
                        const float* __restrict__ fcW2, const float* __restrict__ fcb2,
                        const float* __restrict__ W2,   const float* __restrict__ b2)
{
    int t = threadIdx.x;
    if (blockIdx.x == 0) {
        if (t < 40) {
            int i = t >> 1, j = t & 1;
            float s = 0.f;
#pragma unroll
            for (int k = 0; k < 32; k++) s = fmaf(emb0[i * 32 + k], fcW1[(66 + k) * 2 + j], s);
            d_C[t] = s;
        } else if (t < 80) {
            int u = t - 40;
            int i = u >> 1, j = u & 1;
            float s = 0.f;
#pragma unroll
            for (int k = 0; k < 32; k++) s = fmaf(emb1[i * 32 + k], fcW1[(98 + k) * 2 + j], s);
            d_C[t] = s;
        } else if (t < 92) {
            int u = t - 80;
            float v;
            if (u < 4)       v = fcW1[128 + u];
            else if (u < 6)  v = fcb1[u - 4];
            else if (u < 10) v = fcW2[u - 6];
            else             v = fcb2[u - 10];
            d_C[t] = v;
        } else if (t < 94) {
            int j = t - 92;                       // b2 @ P
            float s = 0.f;
#pragma unroll
            for (int f = 0; f < 64; f++) s = fmaf(b2[f], fcW1[f * 2 + j], s);
            d_C[t] = s;
        } else if (t >= 128) {
            int u = t - 128;                      // W2 @ P : 64x2
            int k = u >> 1, j = u & 1;
            float s = 0.f;
#pragma unroll
            for (int f = 0; f < 64; f++) s = fmaf(W2[k * 64 + f], fcW1[f * 2 + j], s);
            d_W2P[u] = s;
        }
    }
    int base = (blockIdx.x * 256 + t) * 4;
    if (base < NE) {
        int4 d4 = *(const int4*)(dst + base);
        atomicAdd(&d_deg[d4.x], 1);
        atomicAdd(&d_deg[d4.y], 1);
        atomicAdd(&d_deg[d4.z], 1);
        atomicAdd(&d_deg[d4.w], 1);
    }
}

// -------- 2: per-1024-chunk partial sums --------
__global__ void k_scanA()
{
    __shared__ int sred[1024];
    int t = threadIdx.x;
    int i = blockIdx.x * 1024 + t;
    sred[t] = (i < NN) ? d_deg[i] : 0;
    __syncthreads();
#pragma unroll
    for (int o = 512; o > 0; o >>= 1) {
        if (t < o) sred[t] += sred[t + o];
        __syncthreads();
    }
    if (t == 0) d_part[blockIdx.x] = sred[0];
}

// -------- 3: offsets/cursor/dinv; block computes own chunk prefix; re-zero d_deg --------
__global__ void k_scanC()
{
    __shared__ int swarp[32];
    __shared__ int sbase;
    int t = threadIdx.x, lane = t & 31, wid = t >> 5;
    int bid = blockIdx.x;

    if (t == 0) {
        int run = 0;
        for (int j = 0; j < bid; j++) run += d_part[j];
        sbase = run;
        if (bid == 0) d_off[NN] = NE;
    }

    int i = bid * 1024 + t;
    int deg = (i < NN) ? d_deg[i] : 0;
    int v = deg;
#pragma unroll
    for (int o = 1; o < 32; o <<= 1) {
        int u = __shfl_up_sync(0xffffffffu, v, o);
        if (lane >= o) v += u;
    }
    if (lane == 31) swarp[wid] = v;
    __syncthreads();
    if (wid == 0) {
        int w = swarp[lane];
        int wv = w;
#pragma unroll
        for (int o = 1; o < 32; o <<= 1) {
            int u = __shfl_up_sync(0xffffffffu, wv, o);
            if (lane >= o) wv += u;
        }
        swarp[lane] = wv - w;
    }
    __syncthreads();
    if (i < NN) {
        int off = sbase + swarp[wid] + (v - deg);
        d_off[i] = off;
        d_cur[i] = off;
        d_dinv[i] = rsqrtf((float)(deg + 1));
        d_deg[i] = 0;
    }
}

// -------- GEMM: d_bufA = x @ W1. 8x8 per thread, 128-node tile, 128 threads --------
__global__ void __launch_bounds__(128) k_gemm(const float* __restrict__ X,
                                              const float* __restrict__ W)
{
    __shared__ float Xs[128 * 68];
    __shared__ float Ws[64 * 64];

    int t = threadIdx.x;
    int n0 = blockIdx.x * 128;

    {
        const float4* W4 = (const float4*)W;
        float4* Ws4 = (float4*)Ws;
#pragma unroll
        for (int i = 0; i < 8; i++) Ws4[t + i * 128] = W4[t + i * 128];
    }
    {
        const float4* Xg = (const float4*)(X + (size_t)n0 * 64);
#pragma unroll
        for (int i = 0; i < 16; i++) {
            int f = t + i * 128;
            int row = f >> 4, c4 = f & 15;
            float4 v = (n0 + row < NN) ? Xg[f] : make_float4(0.f, 0.f, 0.f, 0.f);
            *(float4*)(Xs + row * 68 + c4 * 4) = v;
        }
    }
    __syncthreads();

    int tx = t & 7;
    int ty = t >> 3;
    int tn = tx * 8;
    int tm = ty * 8;

    float acc[8][8];
#pragma unroll
    for (int i = 0; i < 8; i++)
#pragma unroll
        for (int j = 0; j < 8; j++) acc[i][j] = 0.f;

#pragma unroll 4
    for (int k = 0; k < 64; k++) {
        float4 wa = *(const float4*)(Ws + k * 64 + tn);
        float4 wb = *(const float4*)(Ws + k * 64 + tn + 4);
        float xv[8];
#pragma unroll
        for (int i = 0; i < 8; i++) xv[i] = Xs[(tm + i) * 68 + k];
#pragma unroll
        for (int i = 0; i < 8; i++) {
            acc[i][0] = fmaf(xv[i], wa.x, acc[i][0]);
            acc[i][1] = fmaf(xv[i], wa.y, acc[i][1]);
            acc[i][2] = fmaf(xv[i], wa.z, acc[i][2]);
            acc[i][3] = fmaf(xv[i], wa.w, acc[i][3]);
            acc[i][4] = fmaf(xv[i], wb.x, acc[i][4]);
            acc[i][5] = fmaf(xv[i], wb.y, acc[i][5]);
            acc[i][6] = fmaf(xv[i], wb.z, acc[i][6]);
            acc[i][7] = fmaf(xv[i], wb.w, acc[i][7]);
        }
    }

#pragma unroll
    for (int i = 0; i < 8; i++) {
        int n = n0 + tm + i;
        if (n < NN) {
            float4* zr = (float4*)((float*)d_bufA + (size_t)n * 64 + tn);
            zr[0] = make_float4(acc[i][0], acc[i][1], acc[i][2], acc[i][3]);
            zr[1] = make_float4(acc[i][4], acc[i][5], acc[i][6], acc[i][7]);
        }
    }
}

// -------- CSR fill, 4 edges/thread --------
__global__ void k_fill(const int* __restrict__ src, const int* __restrict__ dst)
{
    int base = (blockIdx.x * 256 + threadIdx.x) * 4;
    if (base < NE) {
        int4 s4 = *(const int4*)(src + base);
        int4 d4 = *(const int4*)(dst + base);
        float w0 = d_dinv[s4.x];
        float w1 = d_dinv[s4.y];
        float w2 = d_dinv[s4.z];
        float w3 = d_dinv[s4.w];
        int p0 = atomicAdd(&d_cur[d4.x], 1);
        int p1 = atomicAdd(&d_cur[d4.y], 1);
        int p2 = atomicAdd(&d_cur[d4.z], 1);
        int p3 = atomicAdd(&d_cur[d4.w], 1);
        d_csr[p0] = s4.x;  d_csrw[p0] = w0;
        d_csr[p1] = s4.y;  d_csrw[p1] = w1;
        d_csr[p2] = s4.z;  d_csrw[p2] = w2;
        d_csr[p3] = s4.w;  d_csrw[p3] = w3;
    }
}

// -------- layer-1 aggregation + relu + fused projection q[n] = h1[n] @ W2P --------
__global__ void __launch_bounds__(256) k_agg(const float* __restrict__ bias)
{
    int gw = (blockIdx.x * 256 + threadIdx.x) >> 5;
    int lane = threadIdx.x & 31;
    if (gw >= NN) return;
    int n = gw;
    int beg = d_off[n], end = d_off[n + 1];
    float dv = d_dinv[n];

    const float* Z = (const float*)d_bufA;
    float2 z = *(const float2*)(Z + (size_t)n * 64 + 2 * lane);
    float ax = dv * z.x, ay = dv * z.y;

    for (int base = beg; base < end; base += 32) {
        int k = base + lane;
        int   sv = (k < end) ? d_csr[k]  : 0;
        float wv = (k < end) ? d_csrw[k] : 0.f;
        int cnt = end - base; if (cnt > 32) cnt = 32;
        for (int j = 0; j < cnt; j += 8) {
            float2 v[8];
            float  w[8];
#pragma unroll
            for (int i = 0; i < 8; i++) {
                int s = __shfl_sync(0xffffffffu, sv, j + i);
                w[i]  = __shfl_sync(0xffffffffu, wv, j + i);
                v[i]  = *(const float2*)(Z + (size_t)s * 64 + 2 * lane);
            }
#pragma unroll
            for (int i = 0; i < 8; i++) {
                ax = fmaf(w[i], v[i].x, ax);
                ay = fmaf(w[i], v[i].y, ay);
            }
        }
    }

    float2 bb = *(const float2*)(bias + 2 * lane);
    float hx = fmaxf(fmaf(dv, ax, bb.x), 0.f);
    float hy = fmaxf(fmaf(dv, ay, bb.y), 0.f);

    // q[n] = h1[n] @ W2P ; lane owns features 2*lane, 2*lane+1
    float4 w = *(const float4*)(d_W2P + 4 * lane);
    float q0 = fmaf(hx, w.x, hy * w.z);
    float q1 = fmaf(hx, w.y, hy * w.w);
#pragma unroll
    for (int o = 16; o > 0; o >>= 1) {
        q0 += __shfl_xor_sync(0xffffffffu, q0, o);
        q1 += __shfl_xor_sync(0xffffffffu, q1, o);
    }
    if (lane == 0) d_q[n] = make_float2(q0, q1);
}

// -------- layer-2 aggregation on 2-wide q: g[n] = dv*(dv*q[n] + sum w_s q[s]) + b2P --------
__global__ void __launch_bounds__(256) k_agg2()
{
    int n = blockIdx.x * 256 + threadIdx.x;
    if (n >= NN) return;
    int beg = d_off[n], end = d_off[n + 1];
    float dv = d_dinv[n];

    float2 q = d_q[n];
    float ax = dv * q.x, ay = dv * q.y;

    for (int base = beg; base < end; base += 8) {
        int cnt = end - base; if (cnt > 8) cnt = 8;
        int    s[8];
        float  w[8];
        float2 v[8];
#pragma unroll
        for (int i = 0; i < 8; i++) {
            int k = base + i;
            s[i] = (i < cnt) ? d_csr[k] : 0;
            w[i] = (i < cnt) ? d_csrw[k] : 0.f;
        }
#pragma unroll
        for (int i = 0; i < 8; i++) v[i] = d_q[s[i]];
#pragma unroll
        for (int i = 0; i < 8; i++) {
            ax = fmaf(w[i], v[i].x, ax);
            ay = fmaf(w[i], v[i].y, ay);
        }
    }

    d_g[n] = make_float2(fmaf(dv, ax, d_C[92]), fmaf(dv, ay, d_C[93]));
}

// -------- edge head: 4 edges/thread --------
__global__ void __launch_bounds__(256) k_edge(const int* __restrict__ src,
                                              const int* __restrict__ dst,
                                              const int* __restrict__ attr,
                                              float4* __restrict__ out)
{
    __shared__ float Cs[92];
    if (threadIdx.x < 92) Cs[threadIdx.x] = d_C[threadIdx.x];
    __syncthreads();

    int base = (blockIdx.x * 256 + threadIdx.x) * 4;
    if (base >= NE) return;

    int4 s4 = *(const int4*)(src + base);
    int4 d4 = *(const int4*)(dst + base);
    int4 a0 = *(const int4*)(attr + base);
    int4 a1 = *(const int4*)(attr + NE + base);
    int4 a2 = *(const int4*)(attr + 2 * NE + base);
    int4 a3 = *(const int4*)(attr + 3 * NE + base);

    float2 gss[4] = {d_g[s4.x], d_g[s4.y], d_g[s4.z], d_g[s4.w]};
    float2 gdd[4] = {d_g[d4.x], d_g[d4.y], d_g[d4.z], d_g[d4.w]};
    int aa0[4] = {a0.x, a0.y, a0.z, a0.w};
    int aa1[4] = {a1.x, a1.y, a1.z, a1.w};
    int aa2[4] = {a2.x, a2.y, a2.z, a2.w};
    int aa3[4] = {a3.x, a3.y, a3.z, a3.w};

    float r[8];
#pragma unroll
    for (int i = 0; i < 4; i++) {
        float f0 = (float)aa0[i], f1 = (float)aa1[i];
        float u0 = gss[i].x - gdd[i].x + f0 * Cs[80] + f1 * Cs[82]
                 + Cs[aa2[i] * 2]     + Cs[40 + aa3[i] * 2]     + Cs[84];
        float u1 = gss[i].y - gdd[i].y + f0 * Cs[81] + f1 * Cs[83]
                 + Cs[aa2[i] * 2 + 1] + Cs[40 + aa3[i] * 2 + 1] + Cs[85];
        u0 = fmaxf(u0, 0.f);
        u1 = fmaxf(u1, 0.f);
        float v0 = u0 * Cs[86] + u1 * Cs[88] + Cs[90];
        float v1 = u0 * Cs[87] + u1 * Cs[89] + Cs[91];
        float m = fmaxf(v0, v1);
        float lse = m + __logf(__expf(v0 - m) + __expf(v1 - m));
        r[i * 2]     = v0 - lse;
        r[i * 2 + 1] = v1 - lse;
    }

    out[base >> 1]       = make_float4(r[0], r[1], r[2], r[3]);
    out[(base >> 1) + 1] = make_float4(r[4], r[5], r[6], r[7]);
}

extern "C" void kernel_launch(void* const* d_in, const int* in_sizes, int n_in,
                              void* d_out, int out_size)
{
    const float* x    = (const float*)d_in[0];
    const int*   ei   = (const int*)  d_in[1];
    const int*   ea   = (const int*)  d_in[2];
    const float* W1   = (const float*)d_in[3];
    const float* b1   = (const float*)d_in[4];
    const float* W2   = (const float*)d_in[5];
    const float* b2   = (const float*)d_in[6];
    const float* emb0 = (const float*)d_in[7];
    const float* emb1 = (const float*)d_in[8];
    const float* fcW1 = (const float*)d_in[9];
    const float* fcb1 = (const float*)d_in[10];
    const float* fcW2 = (const float*)d_in[11];
    const float* fcb2 = (const float*)d_in[12];

    const int* src = ei;
    const int* dst = ei + NE;

    int gbE4 = (NE / 4 + 255) / 256;
    int gbG  = (NN + 127) / 128;
    int gbW  = (NN * 32 + 255) / 256;
    int gbN  = (NN + 255) / 256;

    k_count <<<gbE4, 256>>>(dst, emb0, emb1, fcW1, fcb1, fcW2, fcb2, W2, b2);  // 1
    k_scanA <<<NB, 1024>>>();                                                  // 2
    k_scanC <<<NB, 1024>>>();                                                  // 3
    k_gemm  <<<gbG, 128>>>(x, W1);                                             // 4  <-- ncu capture slot
    k_fill  <<<gbE4, 256>>>(src, dst);                                         // 5
    k_agg   <<<gbW, 256>>>(b1);                                                // 6
    k_agg2  <<<gbN, 256>>>();                                                  // 7
    k_edge  <<<gbE4, 256>>>(src, dst, ea, (float4*)d_out);                     // 8
}

// round 17
// speedup vs baseline: 43.0428x; 1.1191x over previous
#include <cuda_runtime.h>
#include <cuda_fp16.h>

#define NN 100000
#define NE 1600000
#define NB 98   // ceil(NN/1024)

// -------- static scratch; accessed ONLY from device code via symbol --------
__device__ int            d_deg[NN];     // invariant: zero at entry (re-zeroed by scanC)
__device__ int            d_off[NN + 1];
__device__ float          d_dinv[NN];
__device__ unsigned short d_rank[NE];    // within-dst rank of each edge (from count atomics)
__device__ int2           d_csr2[NE];    // {src, bitcast(dinv[src])}
__device__ __half         d_Z[NN * 64];  // Z1 = x @ W1, fp16 storage
__device__ float2         d_q[NN];       // q[n] = relu-h1[n] @ (W2 @ P)
__device__ float2         d_g[NN];
__device__ float          d_C[96];       // [0..39] P0, [40..79] P1, [80..91] scalars, [92..93] b2@P
__device__ float          d_W2P[128];    // (W2 @ fcW1[0:64,0:2]) row-major [k][j]
__device__ int            d_part[NB];

// -------- 1: degree count + rank, 4 edges/thread; block 0 also preps const tables --------
__global__ void k_count(const int* __restrict__ dst,
                        const float* __restrict__ emb0, const float* __restrict__ emb1,
                        const float* __restrict__ fcW1, const float* __restrict__ fcb1,
                        const float* __restrict__ fcW2, const float* __restrict__ fcb2,
                        const float* __restrict__ W2,   const float* __restrict__ b2)
{
    int t = threadIdx.x;
    if (blockIdx.x == 0) {
        if (t < 40) {
            int i = t >> 1, j = t & 1;
            float s = 0.f;
#pragma unroll
            for (int k = 0; k < 32; k++) s = fmaf(emb0[i * 32 + k], fcW1[(66 + k) * 2 + j], s);
            d_C[t] = s;
        } else if (t < 80) {
            int u = t - 40;
            int i = u >> 1, j = u & 1;
            float s = 0.f;
#pragma unroll
            for (int k = 0; k < 32; k++) s = fmaf(emb1[i * 32 + k], fcW1[(98 + k) * 2 + j], s);
            d_C[t] = s;
        } else if (t < 92) {
            int u = t - 80;
            float v;
            if (u < 4)       v = fcW1[128 + u];
            else if (u < 6)  v = fcb1[u - 4];
            else if (u < 10) v = fcW2[u - 6];
            else             v = fcb2[u - 10];
            d_C[t] = v;
        } else if (t < 94) {
            int j = t - 92;                       // b2 @ P
            float s = 0.f;
#pragma unroll
            for (int f = 0; f < 64; f++) s = fmaf(b2[f], fcW1[f * 2 + j], s);
            d_C[t] = s;
        } else if (t >= 128) {
            int u = t - 128;                      // W2 @ P : 64x2
            int k = u >> 1, j = u & 1;
            float s = 0.f;
#pragma unroll
            for (int f = 0; f < 64; f++) s = fmaf(W2[k * 64 + f], fcW1[f * 2 + j], s);
            d_W2P[u] = s;
        }
    }
    int base = (blockIdx.x * 256 + t) * 4;
    if (base < NE) {
        int4 d4 = *(const int4*)(dst + base);
        ushort4 r;
        r.x = (unsigned short)atomicAdd(&d_deg[d4.x], 1);
        r.y = (unsigned short)atomicAdd(&d_deg[d4.y], 1);
        r.z = (unsigned short)atomicAdd(&d_deg[d4.z], 1);
        r.w = (unsigned short)atomicAdd(&d_deg[d4.w], 1);
        *(ushort4*)(d_rank + base) = r;
    }
}

// -------- 2: per-1024-chunk partial sums --------
__global__ void k_scanA()
{
    __shared__ int sred[1024];
    int t = threadIdx.x;
    int i = blockIdx.x * 1024 + t;
    sred[t] = (i < NN) ? d_deg[i] : 0;
    __syncthreads();
#pragma unroll
    for (int o = 512; o > 0; o >>= 1) {
        if (t < o) sred[t] += sred[t + o];
        __syncthreads();
    }
    if (t == 0) d_part[blockIdx.x] = sred[0];
}

// -------- 3: offsets/dinv; block computes own chunk prefix; re-zero d_deg --------
__global__ void k_scanC()
{
    __shared__ int swarp[32];
    __shared__ int sbase;
    int t = threadIdx.x, lane = t & 31, wid = t >> 5;
    int bid = blockIdx.x;

    if (t == 0) {
        int run = 0;
        for (int j = 0; j < bid; j++) run += d_part[j];
        sbase = run;
        if (bid == 0) d_off[NN] = NE;
    }

    int i = bid * 1024 + t;
    int deg = (i < NN) ? d_deg[i] : 0;
    int v = deg;
#pragma unroll
    for (int o = 1; o < 32; o <<= 1) {
        int u = __shfl_up_sync(0xffffffffu, v, o);
        if (lane >= o) v += u;
    }
    if (lane == 31) swarp[wid] = v;
    __syncthreads();
    if (wid == 0) {
        int w = swarp[lane];
        int wv = w;
#pragma unroll
        for (int o = 1; o < 32; o <<= 1) {
            int u = __shfl_up_sync(0xffffffffu, wv, o);
            if (lane >= o) wv += u;
        }
        swarp[lane] = wv - w;
    }
    __syncthreads();
    if (i < NN) {
        d_off[i] = sbase + swarp[wid] + (v - deg);
        d_dinv[i] = rsqrtf((float)(deg + 1));
        d_deg[i] = 0;
    }
}

// -------- GEMM: d_Z(fp16) = x @ W1. 8x8 per thread, 128-node tile, 128 threads --------
__global__ void __launch_bounds__(128) k_gemm(const float* __restrict__ X,
                                              const float* __restrict__ W)
{
    __shared__ float Xs[128 * 68];
    __shared__ float Ws[64 * 64];

    int t = threadIdx.x;
    int n0 = blockIdx.x * 128;

    {
        const float4* W4 = (const float4*)W;
        float4* Ws4 = (float4*)Ws;
#pragma unroll
        for (int i = 0; i < 8; i++) Ws4[t + i * 128] = W4[t + i * 128];
    }
    {
        const float4* Xg = (const float4*)(X + (size_t)n0 * 64);
#pragma unroll
        for (int i = 0; i < 16; i++) {
            int f = t + i * 128;
            int row = f >> 4, c4 = f & 15;
            float4 v = (n0 + row < NN) ? Xg[f] : make_float4(0.f, 0.f, 0.f, 0.f);
            *(float4*)(Xs + row * 68 + c4 * 4) = v;
        }
    }
    __syncthreads();

    int tx = t & 7;
    int ty = t >> 3;
    int tn = tx * 8;
    int tm = ty * 8;

    float acc[8][8];
#pragma unroll
    for (int i = 0; i < 8; i++)
#pragma unroll
        for (int j = 0; j < 8; j++) acc[i][j] = 0.f;

#pragma unroll 4
    for (int k = 0; k < 64; k++) {
        float4 wa = *(const float4*)(Ws + k * 64 + tn);
        float4 wb = *(const float4*)(Ws + k * 64 + tn + 4);
        float xv[8];
#pragma unroll
        for (int i = 0; i < 8; i++) xv[i] = Xs[(tm + i) * 68 + k];
#pragma unroll
        for (int i = 0; i < 8; i++) {
            acc[i][0] = fmaf(xv[i], wa.x, acc[i][0]);
            acc[i][1] = fmaf(xv[i], wa.y, acc[i][1]);
            acc[i][2] = fmaf(xv[i], wa.z, acc[i][2]);
            acc[i][3] = fmaf(xv[i], wa.w, acc[i][3]);
            acc[i][4] = fmaf(xv[i], wb.x, acc[i][4]);
            acc[i][5] = fmaf(xv[i], wb.y, acc[i][5]);
            acc[i][6] = fmaf(xv[i], wb.z, acc[i][6]);
            acc[i][7] = fmaf(xv[i], wb.w, acc[i][7]);
        }
    }

#pragma unroll
    for (int i = 0; i < 8; i++) {
        int n = n0 + tm + i;
        if (n < NN) {
            __half2 hh[4];
            hh[0] = __floats2half2_rn(acc[i][0], acc[i][1]);
            hh[1] = __floats2half2_rn(acc[i][2], acc[i][3]);
            hh[2] = __floats2half2_rn(acc[i][4], acc[i][5]);
            hh[3] = __floats2half2_rn(acc[i][6], acc[i][7]);
            *(uint4*)(d_Z + (size_t)n * 64 + tn) = *(const uint4*)hh;
        }
    }
}

// -------- CSR fill, 4 edges/thread, NO atomics (rank precomputed) --------
__global__ void k_fill(const int* __restrict__ src, const int* __restrict__ dst)
{
    int base = (blockIdx.x * 256 + threadIdx.x) * 4;
    if (base < NE) {
        int4 s4 = *(const int4*)(src + base);
        int4 d4 = *(const int4*)(dst + base);
        ushort4 r4 = *(const ushort4*)(d_rank + base);
        int p0 = d_off[d4.x] + r4.x;
        int p1 = d_off[d4.y] + r4.y;
        int p2 = d_off[d4.z] + r4.z;
        int p3 = d_off[d4.w] + r4.w;
        d_csr2[p0] = make_int2(s4.x, __float_as_int(d_dinv[s4.x]));
        d_csr2[p1] = make_int2(s4.y, __float_as_int(d_dinv[s4.y]));
        d_csr2[p2] = make_int2(s4.z, __float_as_int(d_dinv[s4.z]));
        d_csr2[p3] = make_int2(s4.w, __float_as_int(d_dinv[s4.w]));
    }
}

// -------- layer-1 aggregation + relu + fused projection q[n] = h1[n] @ W2P --------
__global__ void __launch_bounds__(256) k_agg(const float* __restrict__ bias)
{
    int gw = (blockIdx.x * 256 + threadIdx.x) >> 5;
    int lane = threadIdx.x & 31;
    if (gw >= NN) return;
    int n = gw;
    int beg = d_off[n], end = d_off[n + 1];
    float dv = d_dinv[n];

    const __half2* Z2 = (const __half2*)d_Z;
    float2 z = __half22float2(Z2[(size_t)n * 32 + lane]);
    float ax = dv * z.x, ay = dv * z.y;

    for (int base = beg; base < end; base += 32) {
        int k = base + lane;
        int2 pr = (k < end) ? d_csr2[k] : make_int2(0, 0);
        int cnt = end - base; if (cnt > 32) cnt = 32;
        for (int j = 0; j < cnt; j += 8) {
            __half2 hv[8];
            float   w[8];
#pragma unroll
            for (int i = 0; i < 8; i++) {
                int s = __shfl_sync(0xffffffffu, pr.x, j + i);
                w[i]  = __int_as_float(__shfl_sync(0xffffffffu, pr.y, j + i));
                hv[i] = Z2[(size_t)s * 32 + lane];
            }
#pragma unroll
            for (int i = 0; i < 8; i++) {
                float2 v = __half22float2(hv[i]);
                ax = fmaf(w[i], v.x, ax);
                ay = fmaf(w[i], v.y, ay);
            }
        }
    }

    float2 bb = *(const float2*)(bias + 2 * lane);
    float hx = fmaxf(fmaf(dv, ax, bb.x), 0.f);
    float hy = fmaxf(fmaf(dv, ay, bb.y), 0.f);

    float4 w = *(const float4*)(d_W2P + 4 * lane);
    float q0 = fmaf(hx, w.x, hy * w.z);
    float q1 = fmaf(hx, w.y, hy * w.w);
#pragma unroll
    for (int o = 16; o > 0; o >>= 1) {
        q0 += __shfl_xor_sync(0xffffffffu, q0, o);
        q1 += __shfl_xor_sync(0xffffffffu, q1, o);
    }
    if (lane == 0) d_q[n] = make_float2(q0, q1);
}

// -------- layer-2 aggregation on 2-wide q --------
__global__ void __launch_bounds__(256) k_agg2()
{
    int n = blockIdx.x * 256 + threadIdx.x;
    if (n >= NN) return;
    int beg = d_off[n], end = d_off[n + 1];
    float dv = d_dinv[n];

    float2 q = d_q[n];
    float ax = dv * q.x, ay = dv * q.y;

    for (int base = beg; base < end; base += 8) {
        int cnt = end - base; if (cnt > 8) cnt = 8;
        int2   pr[8];
        float2 v[8];
#pragma unroll
        for (int i = 0; i < 8; i++) {
            int k = base + i;
            pr[i] = (i < cnt) ? d_csr2[k] : make_int2(0, 0);
        }
#pragma unroll
        for (int i = 0; i < 8; i++) v[i] = d_q[pr[i].x];
#pragma unroll
        for (int i = 0; i < 8; i++) {
            float w = (i < cnt) ? __int_as_float(pr[i].y) : 0.f;
            ax = fmaf(w, v[i].x, ax);
            ay = fmaf(w, v[i].y, ay);
        }
    }

    d_g[n] = make_float2(fmaf(dv, ax, d_C[92]), fmaf(dv, ay, d_C[93]));
}

// -------- edge head: 4 edges/thread --------
__global__ void __launch_bounds__(256) k_edge(const int* __restrict__ src,
                                              const int* __restrict__ dst,
                                              const int* __restrict__ attr,
                                              float4* __restrict__ out)
{
    __shared__ float Cs[92];
    if (threadIdx.x < 92) Cs[threadIdx.x] = d_C[threadIdx.x];
    __syncthreads();

    int base = (blockIdx.x * 256 + threadIdx.x) * 4;
    if (base >= NE) return;

    int4 s4 = *(const int4*)(src + base);
    int4 d4 = *(const int4*)(dst + base);
    int4 a0 = *(const int4*)(attr + base);
    int4 a1 = *(const int4*)(attr + NE + base);
    int4 a2 = *(const int4*)(attr + 2 * NE + base);
    int4 a3 = *(const int4*)(attr + 3 * NE + base);

    float2 gss[4] = {d_g[s4.x], d_g[s4.y], d_g[s4.z], d_g[s4.w]};
    float2 gdd[4] = {d_g[d4.x], d_g[d4.y], d_g[d4.z], d_g[d4.w]};
    int aa0[4] = {a0.x, a0.y, a0.z, a0.w};
    int aa1[4] = {a1.x, a1.y, a1.z, a1.w};
    int aa2[4] = {a2.x, a2.y, a2.z, a2.w};
    int aa3[4] = {a3.x, a3.y, a3.z, a3.w};

    float r[8];
#pragma unroll
    for (int i = 0; i < 4; i++) {
        float f0 = (float)aa0[i], f1 = (float)aa1[i];
        float u0 = gss[i].x - gdd[i].x + f0 * Cs[80] + f1 * Cs[82]
                 + Cs[aa2[i] * 2]     + Cs[40 + aa3[i] * 2]     + Cs[84];
        float u1 = gss[i].y - gdd[i].y + f0 * Cs[81] + f1 * Cs[83]
                 + Cs[aa2[i] * 2 + 1] + Cs[40 + aa3[i] * 2 + 1] + Cs[85];
        u0 = fmaxf(u0, 0.f);
        u1 = fmaxf(u1, 0.f);
        float v0 = u0 * Cs[86] + u1 * Cs[88] + Cs[90];
        float v1 = u0 * Cs[87] + u1 * Cs[89] + Cs[91];
        float m = fmaxf(v0, v1);
        float lse = m + __logf(__expf(v0 - m) + __expf(v1 - m));
        r[i * 2]     = v0 - lse;
        r[i * 2 + 1] = v1 - lse;
    }

    out[base >> 1]       = make_float4(r[0], r[1], r[2], r[3]);
    out[(base >> 1) + 1] = make_float4(r[4], r[5], r[6], r[7]);
}

extern "C" void kernel_launch(void* const* d_in, const int* in_sizes, int n_in,
                              void* d_out, int out_size)
{
    const float* x    = (const float*)d_in[0];
    const int*   ei   = (const int*)  d_in[1];
    const int*   ea   = (const int*)  d_in[2];
    const float* W1   = (const float*)d_in[3];
    const float* b1   = (const float*)d_in[4];
    const float* W2   = (const float*)d_in[5];
    const float* b2   = (const float*)d_in[6];
    const float* emb0 = (const float*)d_in[7];
    const float* emb1 = (const float*)d_in[8];
    const float* fcW1 = (const float*)d_in[9];
    const float* fcb1 = (const float*)d_in[10];
    const float* fcW2 = (const float*)d_in[11];
    const float* fcb2 = (const float*)d_in[12];

    const int* src = ei;
    const int* dst = ei + NE;

    int gbE4 = (NE / 4 + 255) / 256;
    int gbG  = (NN + 127) / 128;
    int gbW  = (NN * 32 + 255) / 256;
    int gbN  = (NN + 255) / 256;

    k_count <<<gbE4, 256>>>(dst, emb0, emb1, fcW1, fcb1, fcW2, fcb2, W2, b2);  // 1
    k_scanA <<<NB, 1024>>>();                                                  // 2
    k_scanC <<<NB, 1024>>>();                                                  // 3
    k_gemm  <<<gbG, 128>>>(x, W1);                                             // 4  <-- ncu capture slot
    k_fill  <<<gbE4, 256>>>(src, dst);                                         // 5
    k_agg   <<<gbW, 256>>>(b1);                                                // 6
    k_agg2  <<<gbN, 256>>>();                                                  // 7
    k_edge  <<<gbE4, 256>>>(src, dst, ea, (float4*)d_out);                     // 8
}